// round 16
// baseline (speedup 1.0000x reference)
#include <cuda_runtime.h>
#include <cuda_fp16.h>
#include <math.h>
#include <stdint.h>

#define N0_ 60000
#define N1_ 15000
#define N2_ 3750
#define K_  32
#define P_  15
#define MP1 15104   // N1 padded to 128
#define MP2 3840    // N2 padded to 64/128

// ---------------- intermediate buffers (device globals; no allocations) ----------
__device__ __align__(16) __half g_f1 [N0_*64];        // skip0
__device__ __align__(16) __half g_f2 [N1_*64];
__device__ __align__(16) __half g_f3 [N1_*128];       // skip1
__device__ __align__(16) __half g_f4 [N2_*128];
__device__ __align__(16) __half g_f5 [N2_*256];
__device__ __align__(128) __half g_fk [MP1*960];      // k-blocked fk (14.5M halfs)
__device__ __align__(16) __half g_fu1[N1_*128];
__device__ __align__(16) float  g_ff [N0_*32];
__device__ __align__(128) __half g_wh [976896];       // prepped half weights
__device__ unsigned char g_rsnz[N0_];
__device__ int g_gmax;

#define WOFF_W2  0
#define WOFF_W3  61440
#define WOFF_W4  184320
#define WOFF_W5  430080
#define WOFF_U1  921600
#define WOFF_U2  970752

// ---------------- prep: conv weights -> k-blocked+swizzled; unary -> [N][Kd] -----
__global__ __launch_bounds__(256)
void prep_kernel(const float* __restrict__ W2, const float* __restrict__ W3,
                 const float* __restrict__ W4, const float* __restrict__ W5,
                 const float* __restrict__ Wu1, const float* __restrict__ Wu2,
                 __half* __restrict__ wh)
{
    __shared__ float tile[32][33];
    int b = blockIdx.x;
    if (b == 0 && threadIdx.x == 0) g_gmax = 0;
    const float* src; __half* dst; int Kd, N, gx; bool conv;
    if      (b < 60)  { src=W2;  dst=wh+WOFF_W2; Kd=960;  N=64;  gx=30; conv=true; }
    else if (b < 180) { src=W3;  dst=wh+WOFF_W3; Kd=960;  N=128; gx=30; conv=true;  b-=60; }
    else if (b < 420) { src=W4;  dst=wh+WOFF_W4; Kd=1920; N=128; gx=60; conv=true;  b-=180; }
    else if (b < 900) { src=W5;  dst=wh+WOFF_W5; Kd=1920; N=256; gx=60; conv=true;  b-=420; }
    else if (b < 948) { src=Wu1; dst=wh+WOFF_U1; Kd=384;  N=128; gx=12; conv=false; b-=900; }
    else              { src=Wu2; dst=wh+WOFF_U2; Kd=192;  N=32;  gx=6;  conv=false; b-=948; }
    int kb = (b % gx)*32, nb = (b / gx)*32;
    int tx = threadIdx.x & 31, ty = threadIdx.x >> 5;   // 32 x 8
    #pragma unroll
    for (int r = 0; r < 32; r += 8)
        tile[ty+r][tx] = src[(size_t)(kb+ty+r)*N + nb + tx];
    __syncthreads();
    #pragma unroll
    for (int r = 0; r < 32; r += 8) {
        int nn = nb + ty + r, kc = kb + tx;
        __half v = __float2half(tile[tx][ty+r]);
        if (conv) {
            // blocked: [kblock][N][64], swizzled halfs within 64-half row
            dst[(size_t)(kc>>6)*((size_t)N*64) + (size_t)nn*64 + ((kc&63) ^ ((nn&7)<<3))] = v;
        } else {
            dst[(size_t)nn*Kd + kc] = v;
        }
    }
}

// ---------------- layer 1: KPConv Cin=1 Cout=64 ----------------------------------
__global__ __launch_bounds__(256)
void conv1_kernel(const float* __restrict__ pts, const int* __restrict__ neigh,
                  const float* __restrict__ feats, const float* __restrict__ kp,
                  const float* __restrict__ W1, __half* __restrict__ out)
{
    const float extent = 0.5f;
    __shared__ float sdiff[4][K_][3];
    __shared__ float sfeat[4][K_];
    __shared__ float sinfl[4][K_*P_];
    __shared__ float sfk[4][P_];
    int pt = threadIdx.x >> 6;
    int t  = threadIdx.x & 63;
    int n  = blockIdx.x * 4 + pt;
    if (t < K_) {
        int idx = neigh[n*K_+t];
        float qx = pts[n*3+0], qy = pts[n*3+1], qz = pts[n*3+2];
        sdiff[pt][t][0] = pts[idx*3+0]-qx;
        sdiff[pt][t][1] = pts[idx*3+1]-qy;
        sdiff[pt][t][2] = pts[idx*3+2]-qz;
        sfeat[pt][t] = feats[idx];
    }
    __syncthreads();
    for (int i = t; i < K_*P_; i += 64) {
        int k = i / P_, p = i % P_;
        float dx = sdiff[pt][k][0] - kp[p*3+0]*extent;
        float dy = sdiff[pt][k][1] - kp[p*3+1]*extent;
        float dz = sdiff[pt][k][2] - kp[p*3+2]*extent;
        float dist = sqrtf(dx*dx+dy*dy+dz*dz);
        sinfl[pt][i] = fmaxf(0.f, 1.f - dist/extent);
    }
    __syncthreads();
    if (t < P_) {
        float acc = 0.f;
        #pragma unroll
        for (int k = 0; k < K_; k++) acc += sinfl[pt][k*P_+t]*sfeat[pt][k];
        sfk[pt][t] = acc;
    }
    __syncthreads();
    float acc = 0.f;
    #pragma unroll
    for (int p = 0; p < P_; p++) acc += sfk[pt][p]*W1[p*64+t];
    out[n*64+t] = __float2half(acc > 0.f ? acc : 0.1f*acc);
}

// ---------------- tensor-core gather -> k-blocked+swizzled fk --------------------
__device__ __forceinline__ void ldsm4t(uint32_t& r0, uint32_t& r1, uint32_t& r2,
                                       uint32_t& r3, uint32_t addr)
{
    asm volatile("ldmatrix.sync.aligned.m8n8.x4.trans.shared.b16 {%0,%1,%2,%3}, [%4];"
                 : "=r"(r0), "=r"(r1), "=r"(r2), "=r"(r3) : "r"(addr));
}

template<int CIN, int WPB>
__global__ __launch_bounds__(32*WPB)
void gather_mma_kernel(const float* __restrict__ qpts, const float* __restrict__ spts,
                       const int* __restrict__ neigh, const __half* __restrict__ feats,
                       const float* __restrict__ kp, float extent,
                       __half* __restrict__ fk, int Npts, int Mpad)
{
    constexpr int STR = CIN + 8;
    constexpr int MT  = CIN / 16;
    __shared__ __half nf[WPB][32][STR];
    __shared__ float  sdiff[WPB][32][4];
    __shared__ int    sidx[WPB][32];

    const int w    = threadIdx.x >> 5;
    const int lane = threadIdx.x & 31;
    const int n    = blockIdx.x * WPB + w;
    if (n >= Npts) return;
    const int g = lane >> 2, t4 = lane & 3;

    {
        int idx = neigh[n*K_ + lane];
        sidx[w][lane] = idx;
        float qx = qpts[n*3+0], qy = qpts[n*3+1], qz = qpts[n*3+2];
        sdiff[w][lane][0] = spts[idx*3+0]-qx;
        sdiff[w][lane][1] = spts[idx*3+1]-qy;
        sdiff[w][lane][2] = spts[idx*3+2]-qz;
    }
    __syncwarp();

    if (CIN == 64) {
        #pragma unroll
        for (int r = 0; r < 8; r++) {
            int row = r*4 + (lane>>3);
            int ch  = (lane&7)*8;
            uint4 v = *(const uint4*)(feats + (size_t)sidx[w][row]*CIN + ch);
            *(uint4*)&nf[w][row][ch] = v;
        }
    } else {
        #pragma unroll
        for (int r = 0; r < 16; r++) {
            int row = r*2 + (lane>>4);
            int ch  = (lane&15)*8;
            uint4 v = *(const uint4*)(feats + (size_t)sidx[w][row]*CIN + ch);
            *(uint4*)&nf[w][row][ch] = v;
        }
    }

    const float inv_e = 1.0f / extent;
    uint32_t bfr[2][2][2];
    #pragma unroll
    for (int nt = 0; nt < 2; nt++) {
        int p = nt*8 + g;
        bool pv = p < P_;
        float px = 0.f, py = 0.f, pz = 0.f;
        if (pv) {
            px = kp[p*3+0]*extent; py = kp[p*3+1]*extent; pz = kp[p*3+2]*extent;
        }
        #pragma unroll
        for (int ks = 0; ks < 2; ks++) {
            int kb = ks*16 + 2*t4;
            float v[4];
            #pragma unroll
            for (int j = 0; j < 4; j++) {
                int k = kb + (j>>1)*8 + (j&1);
                float dx = sdiff[w][k][0]-px;
                float dy = sdiff[w][k][1]-py;
                float dz = sdiff[w][k][2]-pz;
                float d = sqrtf(dx*dx+dy*dy+dz*dz);
                v[j] = pv ? fmaxf(0.f, 1.f - d*inv_e) : 0.f;
            }
            __half2 h0 = __floats2half2_rn(v[0], v[1]);
            __half2 h1 = __floats2half2_rn(v[2], v[3]);
            bfr[nt][ks][0] = *reinterpret_cast<uint32_t*>(&h0);
            bfr[nt][ks][1] = *reinterpret_cast<uint32_t*>(&h1);
        }
    }
    __syncwarp();

    float d[MT][2][4];
    #pragma unroll
    for (int mt = 0; mt < MT; mt++)
        #pragma unroll
        for (int nt = 0; nt < 2; nt++) {
            d[mt][nt][0]=0.f; d[mt][nt][1]=0.f; d[mt][nt][2]=0.f; d[mt][nt][3]=0.f;
        }
    uint32_t nf_base = (uint32_t)__cvta_generic_to_shared(&nf[w][0][0]);
    const int grp = lane >> 3, jj = lane & 7;
    #pragma unroll
    for (int mt = 0; mt < MT; mt++) {
        #pragma unroll
        for (int ks = 0; ks < 2; ks++) {
            int krow = ks*16 + ((grp & 2) ? 8 : 0) + jj;
            int mcol = mt*16 + ((grp & 1) ? 8 : 0);
            uint32_t addr = nf_base + (uint32_t)(krow*STR + mcol)*2u;
            uint32_t a0,a1,a2,a3;
            ldsm4t(a0,a1,a2,a3, addr);
            #pragma unroll
            for (int nt = 0; nt < 2; nt++)
                asm volatile(
                    "mma.sync.aligned.m16n8k16.row.col.f32.f16.f16.f32 "
                    "{%0,%1,%2,%3},{%4,%5,%6,%7},{%8,%9},{%0,%1,%2,%3};\n"
                    : "+f"(d[mt][nt][0]), "+f"(d[mt][nt][1]),
                      "+f"(d[mt][nt][2]), "+f"(d[mt][nt][3])
                    : "r"(a0), "r"(a1), "r"(a2), "r"(a3),
                      "r"(bfr[nt][ks][0]), "r"(bfr[nt][ks][1]));
        }
    }
    __syncwarp();

    #pragma unroll
    for (int mt = 0; mt < MT; mt++) {
        int c = mt*16 + g;
        #pragma unroll
        for (int nt = 0; nt < 2; nt++) {
            int p0 = nt*8 + 2*t4;
            nf[w][p0  ][c  ] = __float2half(d[mt][nt][0]);
            nf[w][p0+1][c  ] = __float2half(d[mt][nt][1]);
            nf[w][p0  ][c+8] = __float2half(d[mt][nt][2]);
            nf[w][p0+1][c+8] = __float2half(d[mt][nt][3]);
        }
    }
    __syncwarp();
    // store k-blocked: dst = kblock*(Mpad*64) + n*64 + swizzled chunk
    constexpr int CH = P_ * CIN / 8;
    const int nsw = n & 7;
    #pragma unroll
    for (int cid = lane; cid < CH; cid += 32) {
        int p = cid / (CIN/8), cc = cid % (CIN/8);
        int lh = p*CIN + cc*8;
        int kb = lh >> 6;
        int c0 = lh & 63;
        int phys = c0 ^ (nsw << 3);
        uint4 v = *(const uint4*)&nf[w][p][cc*8];
        *(uint4*)(fk + (size_t)kb*((size_t)Mpad*64) + (size_t)n*64 + phys) = v;
    }
}

// ================= conv GEMM: bulk-async A/B, 4-stage mbarrier pipeline ==========
// A: fk blocked [kblock][Mpad][64] swizzled; Bt blocked [kblock][Nw][64] swizzled.
// C[M,N] = leaky(A@B^T) in half. One cp.async.bulk per matrix per stage.
template<int MF, int NF>
__global__ __launch_bounds__(256)
void gemm_bulk(const __half* __restrict__ A, const __half* __restrict__ Bt,
               __half* __restrict__ C, int M, int Mpad, int Nw, int N, int Kd)
{
    constexpr int BM = MF*64, BN = NF*64;
    extern __shared__ __align__(128) __half dynsm[];
    __half* As = dynsm;                   // 4 stages x BM*64
    __half* Bs = dynsm + 4*BM*64;         // 4 stages x BN*64
    __shared__ __align__(8) uint64_t mbars[4];

    const int bm = blockIdx.y * BM, bn = blockIdx.x * BN;
    const int tid = threadIdx.x;
    const int warp = tid >> 5, lane = tid & 31;
    const int wm = warp >> 1, wn = warp & 1;
    const int g = lane >> 2, tg = lane & 3;
    const int nk = Kd >> 6;

    if (tid == 0) {
        #pragma unroll
        for (int s = 0; s < 4; s++) {
            uint32_t a = (uint32_t)__cvta_generic_to_shared(&mbars[s]);
            asm volatile("mbarrier.init.shared.b64 [%0], 1;" :: "r"(a) : "memory");
        }
    }
    __syncthreads();

    auto issue = [&](int s, int kt) {
        if (tid == 0) {
            uint32_t mbar = (uint32_t)__cvta_generic_to_shared(&mbars[s]);
            asm volatile("mbarrier.arrive.expect_tx.shared.b64 _, [%0], %1;"
                         :: "r"(mbar), "r"((BM+BN)*128) : "memory");
            uint32_t da = (uint32_t)__cvta_generic_to_shared(As + s*BM*64);
            const __half* sa = A + ((size_t)kt*Mpad + bm)*64;
            asm volatile("cp.async.bulk.shared::cluster.global.mbarrier::complete_tx::bytes [%0], [%1], %2, [%3];"
                         :: "r"(da), "l"(sa), "r"(BM*128), "r"(mbar) : "memory");
            uint32_t db = (uint32_t)__cvta_generic_to_shared(Bs + s*BN*64);
            const __half* sb = Bt + ((size_t)kt*Nw + bn)*64;
            asm volatile("cp.async.bulk.shared::cluster.global.mbarrier::complete_tx::bytes [%0], [%1], %2, [%3];"
                         :: "r"(db), "l"(sb), "r"(BN*128), "r"(mbar) : "memory");
        }
    };

    float c[MF][4*NF][4];
    #pragma unroll
    for (int i = 0; i < MF; i++)
        #pragma unroll
        for (int j = 0; j < 4*NF; j++) {
            c[i][j][0]=0.f; c[i][j][1]=0.f; c[i][j][2]=0.f; c[i][j][3]=0.f;
        }

    issue(0, 0);
    if (nk > 1) issue(1, 1);
    if (nk > 2) issue(2, 2);

    for (int kt = 0; kt < nk; kt++) {
        int st = kt & 3, parity = (kt >> 2) & 1;
        uint32_t mbar = (uint32_t)__cvta_generic_to_shared(&mbars[st]);
        asm volatile(
            "{\n\t.reg .pred P;\n"
            "W%=:\n\tmbarrier.try_wait.parity.shared.b64 P, [%0], %1;\n"
            "\t@P bra D%=;\n\tbra W%=;\nD%=:\n\t}"
            :: "r"(mbar), "r"(parity) : "memory");
        __syncthreads();

        int nx = kt + 3;
        if (nx < nk) issue(nx & 3, nx);

        const __half* Ast = As + st*BM*64;
        const __half* Bst = Bs + st*BN*64;
        #pragma unroll
        for (int k0 = 0; k0 < 64; k0 += 16) {
            uint32_t a[MF][4], bf[4*NF][2];
            #pragma unroll
            for (int i = 0; i < MF; i++) {
                int r = wm * MF * 16 + i * 16 + g;
                int sw = (r & 7) << 3;
                int h0 = (k0 + 2*tg) ^ sw;
                int h1 = (k0 + 2*tg + 8) ^ sw;
                a[i][0] = *(const uint32_t*)&Ast[(size_t)r*64 + h0];
                a[i][1] = *(const uint32_t*)&Ast[(size_t)(r+8)*64 + h0];
                a[i][2] = *(const uint32_t*)&Ast[(size_t)r*64 + h1];
                a[i][3] = *(const uint32_t*)&Ast[(size_t)(r+8)*64 + h1];
            }
            #pragma unroll
            for (int j = 0; j < 4*NF; j++) {
                int col = wn * NF * 32 + j * 8 + g;
                int sw = (col & 7) << 3;
                bf[j][0] = *(const uint32_t*)&Bst[(size_t)col*64 + ((k0 + 2*tg) ^ sw)];
                bf[j][1] = *(const uint32_t*)&Bst[(size_t)col*64 + ((k0 + 2*tg + 8) ^ sw)];
            }
            #pragma unroll
            for (int i = 0; i < MF; i++)
                #pragma unroll
                for (int j = 0; j < 4*NF; j++)
                    asm volatile(
                        "mma.sync.aligned.m16n8k16.row.col.f32.f16.f16.f32 "
                        "{%0,%1,%2,%3},{%4,%5,%6,%7},{%8,%9},{%0,%1,%2,%3};\n"
                        : "+f"(c[i][j][0]), "+f"(c[i][j][1]),
                          "+f"(c[i][j][2]), "+f"(c[i][j][3])
                        : "r"(a[i][0]), "r"(a[i][1]), "r"(a[i][2]), "r"(a[i][3]),
                          "r"(bf[j][0]), "r"(bf[j][1]));
        }
    }

    #pragma unroll
    for (int i = 0; i < MF; i++) {
        int r0 = bm + wm * MF * 16 + i * 16 + g;
        #pragma unroll
        for (int j = 0; j < 4*NF; j++) {
            int col = bn + wn * NF * 32 + j * 8 + 2 * tg;
            if (col < N) {
                if (r0 < M) {
                    float v0 = c[i][j][0], v1 = c[i][j][1];
                    v0 = v0 > 0.f ? v0 : 0.1f*v0;  v1 = v1 > 0.f ? v1 : 0.1f*v1;
                    *(__half2*)&C[(size_t)r0 * N + col] = __floats2half2_rn(v0, v1);
                }
                if (r0 + 8 < M) {
                    float v2 = c[i][j][2], v3 = c[i][j][3];
                    v2 = v2 > 0.f ? v2 : 0.1f*v2;  v3 = v3 > 0.f ? v3 : 0.1f*v3;
                    *(__half2*)&C[(size_t)(r0+8) * N + col] = __floats2half2_rn(v2, v3);
                }
            }
        }
    }
}

// ================= decoder GEMM (cp.async, CAT): unchanged R12/R15 ===============
__device__ __forceinline__ void cpasync16(uint32_t dst, const void* src, bool valid) {
    int sz = valid ? 16 : 0;
    asm volatile("cp.async.cg.shared.global [%0], [%1], 16, %2;\n"
                 :: "r"(dst), "l"(src), "r"(sz));
}

template<int MF, int NF, bool LEAKY, bool OUTHALF, bool STATS>
__global__ __launch_bounds__(256)
void gemm_tc(const __half* __restrict__ A, const __half* __restrict__ Bt,
             void* __restrict__ Cv, int M, int N, int Kd,
             const int* __restrict__ upidx, const __half* __restrict__ Askip,
             int c_up, int c_skip, unsigned char* __restrict__ rsnz, int* __restrict__ gmaxp)
{
    constexpr int BM = MF * 64, BN = NF * 64;
    constexpr int AI = BM / 32;
    constexpr int BI = BN / 32;
    extern __shared__ __align__(16) __half dynsm2[];
    __half* As = dynsm2;
    __half* Bs = dynsm2 + 4*BM*72;
    __shared__ float swm[8];

    const int bm = blockIdx.y * BM, bn = blockIdx.x * BN;
    const int tid  = threadIdx.x;
    const int warp = tid >> 5, lane = tid & 31;
    const int wm = warp >> 1, wn = warp & 1;
    const int g  = lane >> 2, tg = lane & 3;

    float c[MF][4*NF][4];
    #pragma unroll
    for (int i = 0; i < MF; i++)
        #pragma unroll
        for (int j = 0; j < 4*NF; j++) {
            c[i][j][0]=0.f; c[i][j][1]=0.f; c[i][j][2]=0.f; c[i][j][3]=0.f;
        }

    const int arow = tid >> 3;
    const int akoff = (tid & 7) * 8;

    int ridx[AI];
    #pragma unroll
    for (int i = 0; i < AI; i++) {
        int r = bm + arow + i * 32;
        ridx[i] = (r < M) ? upidx[r] : 0;
    }

    const int nk = Kd >> 6;

    auto issue = [&](int s, int k0) {
        __half* Ast = As + s * (BM*72);
        #pragma unroll
        for (int i = 0; i < AI; i++) {
            int r = arow + i * 32;
            bool v = (bm + r) < M;
            int kc = k0 + akoff;
            const __half* src = (kc < c_up) ? (A + (size_t)ridx[i] * c_up + kc)
                                            : (Askip + (size_t)(bm + r) * c_skip + (kc - c_up));
            if (!v) src = A;
            cpasync16((uint32_t)__cvta_generic_to_shared(&Ast[r*72 + akoff]), src, v);
        }
        __half* Bst = Bs + s * (BN*72);
        #pragma unroll
        for (int i = 0; i < BI; i++) {
            int r = arow + i * 32;
            bool v = (bn + r) < N;
            const __half* srcb = v ? (Bt + (size_t)(bn + r) * Kd + k0 + akoff) : Bt;
            cpasync16((uint32_t)__cvta_generic_to_shared(&Bst[r*72 + akoff]), srcb, v);
        }
        asm volatile("cp.async.commit_group;\n");
    };

    auto compute = [&](int s) {
        const __half* Ast = As + s * (BM*72);
        const __half* Bst = Bs + s * (BN*72);
        #pragma unroll
        for (int k0 = 0; k0 < 64; k0 += 16) {
            uint32_t a[MF][4], bf[4*NF][2];
            #pragma unroll
            for (int i = 0; i < MF; i++) {
                int r = wm * MF * 16 + i * 16 + g;
                a[i][0] = *(const uint32_t*)&Ast[r*72     + k0 + 2*tg    ];
                a[i][1] = *(const uint32_t*)&Ast[(r+8)*72 + k0 + 2*tg    ];
                a[i][2] = *(const uint32_t*)&Ast[r*72     + k0 + 2*tg + 8];
                a[i][3] = *(const uint32_t*)&Ast[(r+8)*72 + k0 + 2*tg + 8];
            }
            #pragma unroll
            for (int j = 0; j < 4*NF; j++) {
                int col = wn * NF * 32 + j * 8 + g;
                bf[j][0] = *(const uint32_t*)&Bst[col*72 + k0 + 2*tg    ];
                bf[j][1] = *(const uint32_t*)&Bst[col*72 + k0 + 2*tg + 8];
            }
            #pragma unroll
            for (int i = 0; i < MF; i++)
                #pragma unroll
                for (int j = 0; j < 4*NF; j++)
                    asm volatile(
                        "mma.sync.aligned.m16n8k16.row.col.f32.f16.f16.f32 "
                        "{%0,%1,%2,%3},{%4,%5,%6,%7},{%8,%9},{%0,%1,%2,%3};\n"
                        : "+f"(c[i][j][0]), "+f"(c[i][j][1]),
                          "+f"(c[i][j][2]), "+f"(c[i][j][3])
                        : "r"(a[i][0]), "r"(a[i][1]), "r"(a[i][2]), "r"(a[i][3]),
                          "r"(bf[j][0]), "r"(bf[j][1]));
        }
    };

    issue(0, 0);
    if (nk > 1) issue(1, 64);  else asm volatile("cp.async.commit_group;\n");
    if (nk > 2) issue(2, 128); else asm volatile("cp.async.commit_group;\n");
    int st = 0;
    for (int kt = 0; kt < nk; kt++) {
        asm volatile("cp.async.wait_group 2;\n");
        __syncthreads();
        compute(st);
        int nx = kt + 3;
        int ws = st + 3; if (ws >= 4) ws -= 4;
        if (nx < nk) issue(ws, nx << 6);
        else asm volatile("cp.async.commit_group;\n");
        if (++st == 4) st = 0;
    }

    __half* Ch = (__half*)Cv;
    float*  Cf = (float*)Cv;
    #pragma unroll
    for (int i = 0; i < MF; i++) {
        int r0 = bm + wm * MF * 16 + i * 16 + g;
        #pragma unroll
        for (int j = 0; j < 4*NF; j++) {
            int col = bn + wn * NF * 32 + j * 8 + 2 * tg;
            if (col < N) {
                if (r0 < M) {
                    float v0 = c[i][j][0], v1 = c[i][j][1];
                    if (LEAKY) { v0 = v0 > 0.f ? v0 : 0.1f*v0; v1 = v1 > 0.f ? v1 : 0.1f*v1; }
                    if (OUTHALF) *(__half2*)&Ch[(size_t)r0 * N + col] = __floats2half2_rn(v0, v1);
                    else { Cf[(size_t)r0 * N + col] = v0; Cf[(size_t)r0 * N + col + 1] = v1; }
                }
                if (r0 + 8 < M) {
                    float v2 = c[i][j][2], v3 = c[i][j][3];
                    if (LEAKY) { v2 = v2 > 0.f ? v2 : 0.1f*v2; v3 = v3 > 0.f ? v3 : 0.1f*v3; }
                    if (OUTHALF) *(__half2*)&Ch[(size_t)(r0+8) * N + col] = __floats2half2_rn(v2, v3);
                    else { Cf[(size_t)(r0+8) * N + col] = v2; Cf[(size_t)(r0+8) * N + col + 1] = v3; }
                }
            }
        }
    }

    if (STATS) {
        float wmax = 0.f;
        if (wn == 0) {
            #pragma unroll
            for (int i = 0; i < MF; i++) {
                float sl = 0.f, sh = 0.f, ml = 0.f, mh = 0.f;
                #pragma unroll
                for (int j = 0; j < 4*NF; j++) {
                    sl += c[i][j][0] + c[i][j][1];
                    sh += c[i][j][2] + c[i][j][3];
                    ml = fmaxf(ml, fmaxf(c[i][j][0], c[i][j][1]));
                    mh = fmaxf(mh, fmaxf(c[i][j][2], c[i][j][3]));
                }
                sl += __shfl_xor_sync(0xffffffffu, sl, 1);
                sl += __shfl_xor_sync(0xffffffffu, sl, 2);
                sh += __shfl_xor_sync(0xffffffffu, sh, 1);
                sh += __shfl_xor_sync(0xffffffffu, sh, 2);
                ml = fmaxf(ml, __shfl_xor_sync(0xffffffffu, ml, 1));
                ml = fmaxf(ml, __shfl_xor_sync(0xffffffffu, ml, 2));
                mh = fmaxf(mh, __shfl_xor_sync(0xffffffffu, mh, 1));
                mh = fmaxf(mh, __shfl_xor_sync(0xffffffffu, mh, 2));
                int r0 = bm + wm * MF * 16 + i * 16 + g;
                if (tg == 0) {
                    if (r0 < M)     rsnz[r0]     = (sl != 0.f) ? 1 : 0;
                    if (r0 + 8 < M) rsnz[r0 + 8] = (sh != 0.f) ? 1 : 0;
                }
                wmax = fmaxf(wmax, fmaxf(ml, mh));
            }
        }
        #pragma unroll
        for (int o = 16; o; o >>= 1)
            wmax = fmaxf(wmax, __shfl_xor_sync(0xffffffffu, wmax, o));
        if (lane == 0) swm[warp] = wmax;
        __syncthreads();
        if (tid == 0) {
            float bmv = swm[0];
            #pragma unroll
            for (int ww = 1; ww < 8; ww++) bmv = fmaxf(bmv, swm[ww]);
            atomicMax(gmaxp, __float_as_int(fmaxf(bmv, 0.f)));
        }
    }
}

// ---------------- detection head: lazy evaluation (R15-proven) --------------------
__global__ void scores_kernel(const int* __restrict__ neigh, const float* __restrict__ ff,
                              const unsigned char* __restrict__ rsnz,
                              float* __restrict__ out_fnorm, float* __restrict__ out_scores)
{
    int warp = (blockIdx.x*blockDim.x + threadIdx.x) >> 5;
    int lane = threadIdx.x & 31;
    if (warp >= N0_) return;
    float fraw = ff[(size_t)warp*32 + lane];
    float s2 = fraw*fraw;
    #pragma unroll
    for (int o = 16; o; o >>= 1) s2 += __shfl_xor_sync(0xffffffffu, s2, o);
    float nrm = fmaxf(sqrtf(s2), 1e-12f);
    out_fnorm[(size_t)warp*32 + lane] = fraw / nrm;

    int myidx = neigh[(size_t)warp*32 + lane];
    unsigned selfm = __ballot_sync(0xffffffffu, myidx == warp);
    if (selfm == 0u) {
        if (lane == 0) out_scores[warp] = 0.f;
        return;
    }

    float inv = 1.0f / (__int_as_float(g_gmax) + 1e-6f);
    float f = fraw * inv;
    int nz = rsnz[myidx];
    #pragma unroll
    for (int o = 16; o; o >>= 1) nz += __shfl_xor_sync(0xffffffffu, nz, o);
    float nnumf = (float)(nz < 1 ? 1 : nz);

    float sumf = 0.f, nmax = -1e30f;
    #pragma unroll 4
    for (int k = 0; k < K_; k++) {
        int idx = __shfl_sync(0xffffffffu, myidx, k);
        float nf = ff[(size_t)idx*32 + lane] * inv;
        sumf += nf;
        nmax = fmaxf(nmax, nf);
    }
    float mean = sumf / nnumf;
    float x = f - mean;
    float lms = fmaxf(x, 0.f) + log1pf(expf(-fabsf(x)));
    float dmax = f;
    #pragma unroll
    for (int o = 16; o; o >>= 1) dmax = fmaxf(dmax, __shfl_xor_sync(0xffffffffu, dmax, o));
    float sc = lms * f / (1e-6f + dmax);
    float det = (f == nmax) ? 1.f : 0.f;
    #pragma unroll
    for (int o = 16; o; o >>= 1) {
        sc  = fmaxf(sc,  __shfl_xor_sync(0xffffffffu, sc, o));
        det = fmaxf(det, __shfl_xor_sync(0xffffffffu, det, o));
    }
    if (lane == 0) out_scores[warp] = sc * det;
}

// ---------------- launch ----------------------------------------------------------
extern "C" void kernel_launch(void* const* d_in, const int* in_sizes, int n_in,
                              void* d_out, int out_size)
{
    const float* features   = (const float*)d_in[0];
    const float* points0    = (const float*)d_in[1];
    const float* points1    = (const float*)d_in[2];
    const float* points2    = (const float*)d_in[3];
    const int*   neighbors0 = (const int*)d_in[4];
    const int*   neighbors1 = (const int*)d_in[5];
    const int*   neighbors2 = (const int*)d_in[6];
    const int*   pools0     = (const int*)d_in[7];
    const int*   pools1     = (const int*)d_in[8];
    const int*   upsamples0 = (const int*)d_in[9];
    const int*   upsamples1 = (const int*)d_in[10];
    const float* kpoints    = (const float*)d_in[11];
    const float* W1  = (const float*)d_in[12];
    const float* W2  = (const float*)d_in[13];
    const float* W3  = (const float*)d_in[14];
    const float* W4  = (const float*)d_in[15];
    const float* W5  = (const float*)d_in[16];
    const float* Wu1 = (const float*)d_in[17];
    const float* Wu2 = (const float*)d_in[18];
    float* out = (float*)d_out;

    __half *f1,*f2,*f3,*f4,*f5,*fk,*fu1,*wh;
    float *ff;
    unsigned char *rsnz;
    int *gmaxp;
    cudaGetSymbolAddress((void**)&f1,  g_f1);
    cudaGetSymbolAddress((void**)&f2,  g_f2);
    cudaGetSymbolAddress((void**)&f3,  g_f3);
    cudaGetSymbolAddress((void**)&f4,  g_f4);
    cudaGetSymbolAddress((void**)&f5,  g_f5);
    cudaGetSymbolAddress((void**)&fk,  g_fk);
    cudaGetSymbolAddress((void**)&fu1, g_fu1);
    cudaGetSymbolAddress((void**)&wh,  g_wh);
    cudaGetSymbolAddress((void**)&ff,  g_ff);
    cudaGetSymbolAddress((void**)&rsnz, g_rsnz);
    cudaGetSymbolAddress((void**)&gmaxp, g_gmax);

    // bulk gemm smem: 4 stages * (BM+BN)*64 halfs * 2B
    const int bsm21 = 4*(128+ 64)*64*2;   // 98304
    const int bsm22 = 4*(128+128)*64*2;   // 131072
    const int bsm11 = 4*( 64+ 64)*64*2;   // 65536
    const int bsm12 = 4*( 64+128)*64*2;   // 98304
    cudaFuncSetAttribute(gemm_bulk<2,1>, cudaFuncAttributeMaxDynamicSharedMemorySize, bsm21);
    cudaFuncSetAttribute(gemm_bulk<2,2>, cudaFuncAttributeMaxDynamicSharedMemorySize, bsm22);
    cudaFuncSetAttribute(gemm_bulk<1,1>, cudaFuncAttributeMaxDynamicSharedMemorySize, bsm11);
    cudaFuncSetAttribute(gemm_bulk<1,2>, cudaFuncAttributeMaxDynamicSharedMemorySize, bsm12);

    // decoder gemm smem
    const int sm21 = 4*(128+ 64)*72*2;    // 110592
    const int sm22 = 4*(128+128)*72*2;    // 147456
    cudaFuncSetAttribute(gemm_tc<2,2,true,true,false>,  cudaFuncAttributeMaxDynamicSharedMemorySize, sm22);
    cudaFuncSetAttribute(gemm_tc<2,1,false,false,true>, cudaFuncAttributeMaxDynamicSharedMemorySize, sm21);

    // ---- prep (weights + gmax reset) ----
    prep_kernel<<<954, 256>>>(W2, W3, W4, W5, Wu1, Wu2, wh);

    // ---- encoder ----
    conv1_kernel<<<N0_/4, 256>>>(points0, neighbors0, features, kpoints, W1, f1);

    gather_mma_kernel<64,8><<<N1_/8, 256>>>(points1, points0, pools0, f1, kpoints, 0.5f, fk, N1_, MP1);
    gemm_bulk<2,1><<<dim3(1,118), 256, bsm21>>>(fk, wh+WOFF_W2, f2, N1_, MP1, 64, 64, 960);

    gather_mma_kernel<64,8><<<N1_/8, 256>>>(points1, points1, neighbors1, f2, kpoints, 1.0f, fk, N1_, MP1);
    gemm_bulk<2,2><<<dim3(1,118), 256, bsm22>>>(fk, wh+WOFF_W3, f3, N1_, MP1, 128, 128, 960);

    gather_mma_kernel<128,4><<<(N2_+3)/4, 128>>>(points2, points1, pools1, f3, kpoints, 1.0f, fk, N2_, MP2);
    gemm_bulk<1,1><<<dim3(2,59), 256, bsm11>>>(fk, wh+WOFF_W4, f4, N2_, MP2, 128, 128, 1920);

    gather_mma_kernel<128,4><<<(N2_+3)/4, 128>>>(points2, points2, neighbors2, f4, kpoints, 2.0f, fk, N2_, MP2);
    gemm_bulk<1,2><<<dim3(2,59), 256, bsm12>>>(fk, wh+WOFF_W5, f5, N2_, MP2, 256, 256, 1920);

    // ---- decoder (concat fused into GEMM A-load) ----
    gemm_tc<2,2,true,true,false><<<dim3(1,(N1_+127)/128), 256, sm22>>>(f5, wh+WOFF_U1, fu1, N1_, 128, 384,
                                                                       upsamples1, f3, 256, 128, nullptr, nullptr);
    gemm_tc<2,1,false,false,true><<<dim3(1,(N0_+127)/128), 256, sm21>>>(fu1, wh+WOFF_U2, ff, N0_, 32, 192,
                                                                        upsamples0, f1, 128, 64, rsnz, gmaxp);

    // ---- detection head + outputs ----
    scores_kernel<<<(N0_ + 7)/8, 256>>>(neighbors0, ff, rsnz, out, out + (size_t)N0_*32);
}

// round 17
// speedup vs baseline: 1.0235x; 1.0235x over previous
#include <cuda_runtime.h>
#include <cuda_fp16.h>
#include <math.h>
#include <stdint.h>

#define N0_ 60000
#define N1_ 15000
#define N2_ 3750
#define K_  32
#define P_  15

// ---------------- intermediate buffers (device globals; no allocations) ----------
__device__ __align__(16) __half g_f1 [N0_*64];        // skip0
__device__ __align__(16) __half g_f2 [N1_*64];
__device__ __align__(16) __half g_f3 [N1_*128];       // skip1
__device__ __align__(16) __half g_f4 [N2_*128];
__device__ __align__(16) __half g_f5 [N2_*256];
__device__ __align__(16) __half g_fk [N1_*P_*64];     // reused by all gathers
__device__ __align__(16) __half g_fu1[N1_*128];
__device__ __align__(16) float  g_ff [N0_*32];
__device__ __align__(16) __half g_wh [976896];        // all transposed half weights
__device__ unsigned char g_rsnz[N0_];
__device__ int g_gmax;

#define WOFF_W2  0
#define WOFF_W3  61440
#define WOFF_W4  184320
#define WOFF_W5  430080
#define WOFF_U1  921600
#define WOFF_U2  970752

// ---------------- merged prep (blocks 0..953) + conv1 (blocks 954..) -------------
__global__ __launch_bounds__(256)
void prep_conv1_kernel(const float* __restrict__ W2, const float* __restrict__ W3,
                       const float* __restrict__ W4, const float* __restrict__ W5,
                       const float* __restrict__ Wu1, const float* __restrict__ Wu2,
                       __half* __restrict__ wh,
                       const float* __restrict__ pts, const int* __restrict__ neigh,
                       const float* __restrict__ feats, const float* __restrict__ kp,
                       const float* __restrict__ W1, __half* __restrict__ outf1)
{
    __shared__ float sbuf[2492];
    int b = blockIdx.x;
    if (b < 954) {
        // ---- weight transpose path ----
        if (b == 0 && threadIdx.x == 0) g_gmax = 0;
        const float* src; __half* dst; int Kd, N, gx;
        if      (b < 60)  { src=W2;  dst=wh+WOFF_W2; Kd=960;  N=64;  gx=30; }
        else if (b < 180) { src=W3;  dst=wh+WOFF_W3; Kd=960;  N=128; gx=30; b-=60; }
        else if (b < 420) { src=W4;  dst=wh+WOFF_W4; Kd=1920; N=128; gx=60; b-=180; }
        else if (b < 900) { src=W5;  dst=wh+WOFF_W5; Kd=1920; N=256; gx=60; b-=420; }
        else if (b < 948) { src=Wu1; dst=wh+WOFF_U1; Kd=384;  N=128; gx=12; b-=900; }
        else              { src=Wu2; dst=wh+WOFF_U2; Kd=192;  N=32;  gx=6;  b-=948; }
        int kb = (b % gx)*32, nb = (b / gx)*32;
        int tx = threadIdx.x & 31, ty = threadIdx.x >> 5;   // 32 x 8
        #pragma unroll
        for (int r = 0; r < 32; r += 8)
            sbuf[(ty+r)*33 + tx] = src[(size_t)(kb+ty+r)*N + nb + tx];
        __syncthreads();
        #pragma unroll
        for (int r = 0; r < 32; r += 8)
            dst[(size_t)(nb+ty+r)*Kd + kb + tx] = __float2half(sbuf[tx*33 + ty+r]);
        return;
    }
    // ---- conv1 path: 4 points per block ----
    float* sdiff = sbuf;            // [4][32][3]
    float* sfeat = sbuf + 384;      // [4][32]
    float* sinfl = sbuf + 512;      // [4][480]
    float* sfk   = sbuf + 2432;     // [4][15]
    const float extent = 0.5f;
    int pt = threadIdx.x >> 6;
    int t  = threadIdx.x & 63;
    int n  = (b - 954) * 4 + pt;
    if (t < K_) {
        int idx = neigh[n*K_+t];
        float qx = pts[n*3+0], qy = pts[n*3+1], qz = pts[n*3+2];
        sdiff[pt*96 + t*3 + 0] = pts[idx*3+0]-qx;
        sdiff[pt*96 + t*3 + 1] = pts[idx*3+1]-qy;
        sdiff[pt*96 + t*3 + 2] = pts[idx*3+2]-qz;
        sfeat[pt*32 + t] = feats[idx];
    }
    __syncthreads();
    for (int i = t; i < K_*P_; i += 64) {
        int k = i / P_, p = i % P_;
        float dx = sdiff[pt*96 + k*3 + 0] - kp[p*3+0]*extent;
        float dy = sdiff[pt*96 + k*3 + 1] - kp[p*3+1]*extent;
        float dz = sdiff[pt*96 + k*3 + 2] - kp[p*3+2]*extent;
        float dist = sqrtf(dx*dx+dy*dy+dz*dz);
        sinfl[pt*480 + i] = fmaxf(0.f, 1.f - dist/extent);
    }
    __syncthreads();
    if (t < P_) {
        float acc = 0.f;
        #pragma unroll
        for (int k = 0; k < K_; k++) acc += sinfl[pt*480 + k*P_+t]*sfeat[pt*32 + k];
        sfk[pt*15 + t] = acc;
    }
    __syncthreads();
    float acc = 0.f;
    #pragma unroll
    for (int p = 0; p < P_; p++) acc += sfk[pt*15 + p]*W1[p*64+t];
    outf1[n*64+t] = __float2half(acc > 0.f ? acc : 0.1f*acc);
}

// ---------------- tensor-core gather (verified R6/R7) -----------------------------
__device__ __forceinline__ void ldsm4t(uint32_t& r0, uint32_t& r1, uint32_t& r2,
                                       uint32_t& r3, uint32_t addr)
{
    asm volatile("ldmatrix.sync.aligned.m8n8.x4.trans.shared.b16 {%0,%1,%2,%3}, [%4];"
                 : "=r"(r0), "=r"(r1), "=r"(r2), "=r"(r3) : "r"(addr));
}

template<int CIN, int WPB>
__global__ __launch_bounds__(32*WPB)
void gather_mma_kernel(const float* __restrict__ qpts, const float* __restrict__ spts,
                       const int* __restrict__ neigh, const __half* __restrict__ feats,
                       const float* __restrict__ kp, float extent,
                       __half* __restrict__ fk, int Npts)
{
    constexpr int STR = CIN + 8;
    constexpr int MT  = CIN / 16;
    __shared__ __half nf[WPB][32][STR];
    __shared__ float  sdiff[WPB][32][4];
    __shared__ int    sidx[WPB][32];

    const int w    = threadIdx.x >> 5;
    const int lane = threadIdx.x & 31;
    const int n    = blockIdx.x * WPB + w;
    if (n >= Npts) return;
    const int g = lane >> 2, t4 = lane & 3;

    {
        int idx = neigh[n*K_ + lane];
        sidx[w][lane] = idx;
        float qx = qpts[n*3+0], qy = qpts[n*3+1], qz = qpts[n*3+2];
        sdiff[w][lane][0] = spts[idx*3+0]-qx;
        sdiff[w][lane][1] = spts[idx*3+1]-qy;
        sdiff[w][lane][2] = spts[idx*3+2]-qz;
    }
    __syncwarp();

    if (CIN == 64) {
        #pragma unroll
        for (int r = 0; r < 8; r++) {
            int row = r*4 + (lane>>3);
            int ch  = (lane&7)*8;
            uint4 v = *(const uint4*)(feats + (size_t)sidx[w][row]*CIN + ch);
            *(uint4*)&nf[w][row][ch] = v;
        }
    } else {
        #pragma unroll
        for (int r = 0; r < 16; r++) {
            int row = r*2 + (lane>>4);
            int ch  = (lane&15)*8;
            uint4 v = *(const uint4*)(feats + (size_t)sidx[w][row]*CIN + ch);
            *(uint4*)&nf[w][row][ch] = v;
        }
    }

    const float inv_e = 1.0f / extent;
    uint32_t bfr[2][2][2];
    #pragma unroll
    for (int nt = 0; nt < 2; nt++) {
        int p = nt*8 + g;
        bool pv = p < P_;
        float px = 0.f, py = 0.f, pz = 0.f;
        if (pv) {
            px = kp[p*3+0]*extent; py = kp[p*3+1]*extent; pz = kp[p*3+2]*extent;
        }
        #pragma unroll
        for (int ks = 0; ks < 2; ks++) {
            int kb = ks*16 + 2*t4;
            float v[4];
            #pragma unroll
            for (int j = 0; j < 4; j++) {
                int k = kb + (j>>1)*8 + (j&1);
                float dx = sdiff[w][k][0]-px;
                float dy = sdiff[w][k][1]-py;
                float dz = sdiff[w][k][2]-pz;
                float d = sqrtf(dx*dx+dy*dy+dz*dz);
                v[j] = pv ? fmaxf(0.f, 1.f - d*inv_e) : 0.f;
            }
            __half2 h0 = __floats2half2_rn(v[0], v[1]);
            __half2 h1 = __floats2half2_rn(v[2], v[3]);
            bfr[nt][ks][0] = *reinterpret_cast<uint32_t*>(&h0);
            bfr[nt][ks][1] = *reinterpret_cast<uint32_t*>(&h1);
        }
    }
    __syncwarp();

    float d[MT][2][4];
    #pragma unroll
    for (int mt = 0; mt < MT; mt++)
        #pragma unroll
        for (int nt = 0; nt < 2; nt++) {
            d[mt][nt][0]=0.f; d[mt][nt][1]=0.f; d[mt][nt][2]=0.f; d[mt][nt][3]=0.f;
        }
    uint32_t nf_base = (uint32_t)__cvta_generic_to_shared(&nf[w][0][0]);
    const int grp = lane >> 3, jj = lane & 7;
    #pragma unroll
    for (int mt = 0; mt < MT; mt++) {
        #pragma unroll
        for (int ks = 0; ks < 2; ks++) {
            int krow = ks*16 + ((grp & 2) ? 8 : 0) + jj;
            int mcol = mt*16 + ((grp & 1) ? 8 : 0);
            uint32_t addr = nf_base + (uint32_t)(krow*STR + mcol)*2u;
            uint32_t a0,a1,a2,a3;
            ldsm4t(a0,a1,a2,a3, addr);
            #pragma unroll
            for (int nt = 0; nt < 2; nt++)
                asm volatile(
                    "mma.sync.aligned.m16n8k16.row.col.f32.f16.f16.f32 "
                    "{%0,%1,%2,%3},{%4,%5,%6,%7},{%8,%9},{%0,%1,%2,%3};\n"
                    : "+f"(d[mt][nt][0]), "+f"(d[mt][nt][1]),
                      "+f"(d[mt][nt][2]), "+f"(d[mt][nt][3])
                    : "r"(a0), "r"(a1), "r"(a2), "r"(a3),
                      "r"(bfr[nt][ks][0]), "r"(bfr[nt][ks][1]));
        }
    }
    __syncwarp();

    #pragma unroll
    for (int mt = 0; mt < MT; mt++) {
        int c = mt*16 + g;
        #pragma unroll
        for (int nt = 0; nt < 2; nt++) {
            int p0 = nt*8 + 2*t4;
            nf[w][p0  ][c  ] = __float2half(d[mt][nt][0]);
            nf[w][p0+1][c  ] = __float2half(d[mt][nt][1]);
            nf[w][p0  ][c+8] = __float2half(d[mt][nt][2]);
            nf[w][p0+1][c+8] = __float2half(d[mt][nt][3]);
        }
    }
    __syncwarp();
    constexpr int CH = P_ * CIN / 8;
    #pragma unroll
    for (int cid = lane; cid < CH; cid += 32) {
        int p = cid / (CIN/8), cc = cid % (CIN/8);
        uint4 v = *(const uint4*)&nf[w][p][cc*8];
        *(uint4*)(fk + (size_t)n*(P_*CIN) + cid*8) = v;
    }
}

// ================= fp16 tensor-core GEMM: BK=64, 4-stage cp.async, wait 2 ========
__device__ __forceinline__ void cpasync16(uint32_t dst, const void* src, bool valid) {
    int sz = valid ? 16 : 0;
    asm volatile("cp.async.cg.shared.global [%0], [%1], 16, %2;\n"
                 :: "r"(dst), "l"(src), "r"(sz));
}

template<int MF, int NF, bool LEAKY, bool CAT, bool OUTHALF, bool STATS>
__global__ __launch_bounds__(256)
void gemm_tc(const __half* __restrict__ A, const __half* __restrict__ Bt,
             void* __restrict__ Cv, int M, int N, int Kd,
             const int* __restrict__ upidx, const __half* __restrict__ Askip,
             int c_up, int c_skip, unsigned char* __restrict__ rsnz, int* __restrict__ gmaxp,
             float* __restrict__ out_fnorm)
{
    constexpr int BM = MF * 64, BN = NF * 64;
    constexpr int AI = BM / 32;
    constexpr int BI = BN / 32;
    extern __shared__ __align__(16) __half dynsm[];
    __half* As = dynsm;
    __half* Bs = dynsm + 4*BM*72;
    __shared__ float swm[8];

    const int bm = blockIdx.y * BM, bn = blockIdx.x * BN;
    const int tid  = threadIdx.x;
    const int warp = tid >> 5, lane = tid & 31;
    const int wm = warp >> 1, wn = warp & 1;
    const int g  = lane >> 2, tg = lane & 3;

    float c[MF][4*NF][4];
    #pragma unroll
    for (int i = 0; i < MF; i++)
        #pragma unroll
        for (int j = 0; j < 4*NF; j++) {
            c[i][j][0]=0.f; c[i][j][1]=0.f; c[i][j][2]=0.f; c[i][j][3]=0.f;
        }

    const int arow = tid >> 3;
    const int akoff = (tid & 7) * 8;

    int ridx[AI];
    if (CAT) {
        #pragma unroll
        for (int i = 0; i < AI; i++) {
            int r = bm + arow + i * 32;
            ridx[i] = (r < M) ? upidx[r] : 0;
        }
    }

    const int nk = Kd >> 6;

    auto issue = [&](int s, int k0) {
        __half* Ast = As + s * (BM*72);
        #pragma unroll
        for (int i = 0; i < AI; i++) {
            int r = arow + i * 32;
            bool v = (bm + r) < M;
            int kc = k0 + akoff;
            const __half* src;
            if (CAT) {
                src = (kc < c_up) ? (A + (size_t)ridx[i] * c_up + kc)
                                  : (Askip + (size_t)(bm + r) * c_skip + (kc - c_up));
                if (!v) src = A;
            } else {
                src = v ? (A + (size_t)(bm + r) * Kd + kc) : A;
            }
            cpasync16((uint32_t)__cvta_generic_to_shared(&Ast[r*72 + akoff]), src, v);
        }
        __half* Bst = Bs + s * (BN*72);
        #pragma unroll
        for (int i = 0; i < BI; i++) {
            int r = arow + i * 32;
            bool v = (bn + r) < N;
            const __half* srcb = v ? (Bt + (size_t)(bn + r) * Kd + k0 + akoff) : Bt;
            cpasync16((uint32_t)__cvta_generic_to_shared(&Bst[r*72 + akoff]), srcb, v);
        }
        asm volatile("cp.async.commit_group;\n");
    };

    auto compute = [&](int s) {
        const __half* Ast = As + s * (BM*72);
        const __half* Bst = Bs + s * (BN*72);
        #pragma unroll
        for (int k0 = 0; k0 < 64; k0 += 16) {
            uint32_t a[MF][4], bf[4*NF][2];
            #pragma unroll
            for (int i = 0; i < MF; i++) {
                int r = wm * MF * 16 + i * 16 + g;
                a[i][0] = *(const uint32_t*)&Ast[r*72     + k0 + 2*tg    ];
                a[i][1] = *(const uint32_t*)&Ast[(r+8)*72 + k0 + 2*tg    ];
                a[i][2] = *(const uint32_t*)&Ast[r*72     + k0 + 2*tg + 8];
                a[i][3] = *(const uint32_t*)&Ast[(r+8)*72 + k0 + 2*tg + 8];
            }
            #pragma unroll
            for (int j = 0; j < 4*NF; j++) {
                int col = wn * NF * 32 + j * 8 + g;
                bf[j][0] = *(const uint32_t*)&Bst[col*72 + k0 + 2*tg    ];
                bf[j][1] = *(const uint32_t*)&Bst[col*72 + k0 + 2*tg + 8];
            }
            #pragma unroll
            for (int i = 0; i < MF; i++)
                #pragma unroll
                for (int j = 0; j < 4*NF; j++)
                    asm volatile(
                        "mma.sync.aligned.m16n8k16.row.col.f32.f16.f16.f32 "
                        "{%0,%1,%2,%3},{%4,%5,%6,%7},{%8,%9},{%0,%1,%2,%3};\n"
                        : "+f"(c[i][j][0]), "+f"(c[i][j][1]),
                          "+f"(c[i][j][2]), "+f"(c[i][j][3])
                        : "r"(a[i][0]), "r"(a[i][1]), "r"(a[i][2]), "r"(a[i][3]),
                          "r"(bf[j][0]), "r"(bf[j][1]));
        }
    };

    issue(0, 0);
    if (nk > 1) issue(1, 64);  else asm volatile("cp.async.commit_group;\n");
    if (nk > 2) issue(2, 128); else asm volatile("cp.async.commit_group;\n");
    int st = 0;
    for (int kt = 0; kt < nk; kt++) {
        asm volatile("cp.async.wait_group 2;\n");
        __syncthreads();
        compute(st);
        int nx = kt + 3;
        int ws = st + 3; if (ws >= 4) ws -= 4;
        if (nx < nk) issue(ws, nx << 6);
        else asm volatile("cp.async.commit_group;\n");
        if (++st == 4) st = 0;
    }

    __half* Ch = (__half*)Cv;
    float*  Cf = (float*)Cv;
    #pragma unroll
    for (int i = 0; i < MF; i++) {
        int r0 = bm + wm * MF * 16 + i * 16 + g;
        #pragma unroll
        for (int j = 0; j < 4*NF; j++) {
            int col = bn + wn * NF * 32 + j * 8 + 2 * tg;
            if (col < N) {
                if (r0 < M) {
                    float v0 = c[i][j][0], v1 = c[i][j][1];
                    if (LEAKY) { v0 = v0 > 0.f ? v0 : 0.1f*v0; v1 = v1 > 0.f ? v1 : 0.1f*v1; }
                    if (OUTHALF) *(__half2*)&Ch[(size_t)r0 * N + col] = __floats2half2_rn(v0, v1);
                    else { Cf[(size_t)r0 * N + col] = v0; Cf[(size_t)r0 * N + col + 1] = v1; }
                }
                if (r0 + 8 < M) {
                    float v2 = c[i][j][2], v3 = c[i][j][3];
                    if (LEAKY) { v2 = v2 > 0.f ? v2 : 0.1f*v2; v3 = v3 > 0.f ? v3 : 0.1f*v3; }
                    if (OUTHALF) *(__half2*)&Ch[(size_t)(r0+8) * N + col] = __floats2half2_rn(v2, v3);
                    else { Cf[(size_t)(r0+8) * N + col] = v2; Cf[(size_t)(r0+8) * N + col + 1] = v3; }
                }
            }
        }
    }

    if (STATS) {
        // N <= 32, grid.x == 1: each row's 32 cols live in one quad (wn==0 warps).
        float wmax = 0.f;
        if (wn == 0) {
            #pragma unroll
            for (int i = 0; i < MF; i++) {
                float sl = 0.f, sh = 0.f, ml = 0.f, mh = 0.f, ql = 0.f, qh = 0.f;
                #pragma unroll
                for (int j = 0; j < 4*NF; j++) {
                    sl += c[i][j][0] + c[i][j][1];
                    sh += c[i][j][2] + c[i][j][3];
                    ml = fmaxf(ml, fmaxf(c[i][j][0], c[i][j][1]));
                    mh = fmaxf(mh, fmaxf(c[i][j][2], c[i][j][3]));
                    ql += c[i][j][0]*c[i][j][0] + c[i][j][1]*c[i][j][1];
                    qh += c[i][j][2]*c[i][j][2] + c[i][j][3]*c[i][j][3];
                }
                #pragma unroll
                for (int o = 1; o <= 2; o <<= 1) {
                    sl += __shfl_xor_sync(0xffffffffu, sl, o);
                    sh += __shfl_xor_sync(0xffffffffu, sh, o);
                    ql += __shfl_xor_sync(0xffffffffu, ql, o);
                    qh += __shfl_xor_sync(0xffffffffu, qh, o);
                    ml = fmaxf(ml, __shfl_xor_sync(0xffffffffu, ml, o));
                    mh = fmaxf(mh, __shfl_xor_sync(0xffffffffu, mh, o));
                }
                int r0 = bm + wm * MF * 16 + i * 16 + g;
                float nl = fmaxf(sqrtf(ql), 1e-12f);
                float nh = fmaxf(sqrtf(qh), 1e-12f);
                #pragma unroll
                for (int j = 0; j < 4*NF; j++) {
                    int col = j * 8 + 2 * tg;
                    if (r0 < M) {
                        out_fnorm[(size_t)r0*32 + col]     = c[i][j][0] / nl;
                        out_fnorm[(size_t)r0*32 + col + 1] = c[i][j][1] / nl;
                    }
                    if (r0 + 8 < M) {
                        out_fnorm[(size_t)(r0+8)*32 + col]     = c[i][j][2] / nh;
                        out_fnorm[(size_t)(r0+8)*32 + col + 1] = c[i][j][3] / nh;
                    }
                }
                if (tg == 0) {
                    if (r0 < M)     rsnz[r0]     = (sl != 0.f) ? 1 : 0;
                    if (r0 + 8 < M) rsnz[r0 + 8] = (sh != 0.f) ? 1 : 0;
                }
                wmax = fmaxf(wmax, fmaxf(ml, mh));
            }
        }
        #pragma unroll
        for (int o = 16; o; o >>= 1)
            wmax = fmaxf(wmax, __shfl_xor_sync(0xffffffffu, wmax, o));
        if (lane == 0) swm[warp] = wmax;
        __syncthreads();
        if (tid == 0) {
            float bmv = swm[0];
            #pragma unroll
            for (int ww = 1; ww < 8; ww++) bmv = fmaxf(bmv, swm[ww]);
            atomicMax(gmaxp, __float_as_int(fmaxf(bmv, 0.f)));
        }
    }
}

// ---------------- detection head: score-only lazy evaluation ---------------------
__global__ void scores_kernel(const int* __restrict__ neigh, const float* __restrict__ ff,
                              const unsigned char* __restrict__ rsnz,
                              float* __restrict__ out_scores)
{
    int warp = (blockIdx.x*blockDim.x + threadIdx.x) >> 5;
    int lane = threadIdx.x & 31;
    if (warp >= N0_) return;
    int myidx = neigh[(size_t)warp*32 + lane];
    unsigned selfm = __ballot_sync(0xffffffffu, myidx == warp);
    if (selfm == 0u) {
        if (lane == 0) out_scores[warp] = 0.f;
        return;
    }

    float fraw = ff[(size_t)warp*32 + lane];
    float inv = 1.0f / (__int_as_float(g_gmax) + 1e-6f);
    float f = fraw * inv;
    int nz = rsnz[myidx];
    #pragma unroll
    for (int o = 16; o; o >>= 1) nz += __shfl_xor_sync(0xffffffffu, nz, o);
    float nnumf = (float)(nz < 1 ? 1 : nz);

    float sumf = 0.f, nmax = -1e30f;
    #pragma unroll 4
    for (int k = 0; k < K_; k++) {
        int idx = __shfl_sync(0xffffffffu, myidx, k);
        float nf = ff[(size_t)idx*32 + lane] * inv;
        sumf += nf;
        nmax = fmaxf(nmax, nf);
    }
    float mean = sumf / nnumf;
    float x = f - mean;
    float lms = fmaxf(x, 0.f) + log1pf(expf(-fabsf(x)));
    float dmax = f;
    #pragma unroll
    for (int o = 16; o; o >>= 1) dmax = fmaxf(dmax, __shfl_xor_sync(0xffffffffu, dmax, o));
    float sc = lms * f / (1e-6f + dmax);
    float det = (f == nmax) ? 1.f : 0.f;
    #pragma unroll
    for (int o = 16; o; o >>= 1) {
        sc  = fmaxf(sc,  __shfl_xor_sync(0xffffffffu, sc, o));
        det = fmaxf(det, __shfl_xor_sync(0xffffffffu, det, o));
    }
    if (lane == 0) out_scores[warp] = sc * det;
}

// ---------------- launch ----------------------------------------------------------
extern "C" void kernel_launch(void* const* d_in, const int* in_sizes, int n_in,
                              void* d_out, int out_size)
{
    const float* features   = (const float*)d_in[0];
    const float* points0    = (const float*)d_in[1];
    const float* points1    = (const float*)d_in[2];
    const float* points2    = (const float*)d_in[3];
    const int*   neighbors0 = (const int*)d_in[4];
    const int*   neighbors1 = (const int*)d_in[5];
    const int*   neighbors2 = (const int*)d_in[6];
    const int*   pools0     = (const int*)d_in[7];
    const int*   pools1     = (const int*)d_in[8];
    const int*   upsamples0 = (const int*)d_in[9];
    const int*   upsamples1 = (const int*)d_in[10];
    const float* kpoints    = (const float*)d_in[11];
    const float* W1  = (const float*)d_in[12];
    const float* W2  = (const float*)d_in[13];
    const float* W3  = (const float*)d_in[14];
    const float* W4  = (const float*)d_in[15];
    const float* W5  = (const float*)d_in[16];
    const float* Wu1 = (const float*)d_in[17];
    const float* Wu2 = (const float*)d_in[18];
    float* out = (float*)d_out;

    __half *f1,*f2,*f3,*f4,*f5,*fk,*fu1,*wh;
    float *ff;
    unsigned char *rsnz;
    int *gmaxp;
    cudaGetSymbolAddress((void**)&f1,  g_f1);
    cudaGetSymbolAddress((void**)&f2,  g_f2);
    cudaGetSymbolAddress((void**)&f3,  g_f3);
    cudaGetSymbolAddress((void**)&f4,  g_f4);
    cudaGetSymbolAddress((void**)&f5,  g_f5);
    cudaGetSymbolAddress((void**)&fk,  g_fk);
    cudaGetSymbolAddress((void**)&fu1, g_fu1);
    cudaGetSymbolAddress((void**)&wh,  g_wh);
    cudaGetSymbolAddress((void**)&ff,  g_ff);
    cudaGetSymbolAddress((void**)&rsnz, g_rsnz);
    cudaGetSymbolAddress((void**)&gmaxp, g_gmax);

    // dynamic smem: 4 stages * (BM+BN)*72 halfs * 2B
    const int sm21 = 4*(128+ 64)*72*2;   // 110592
    const int sm22 = 4*(128+128)*72*2;   // 147456
    const int sm11 = 4*( 64+ 64)*72*2;   // 73728
    const int sm12 = 4*( 64+128)*72*2;   // 110592
    cudaFuncSetAttribute(gemm_tc<2,1,true,false,true,false>,  cudaFuncAttributeMaxDynamicSharedMemorySize, sm21);
    cudaFuncSetAttribute(gemm_tc<2,2,true,false,true,false>,  cudaFuncAttributeMaxDynamicSharedMemorySize, sm22);
    cudaFuncSetAttribute(gemm_tc<1,1,true,false,true,false>,  cudaFuncAttributeMaxDynamicSharedMemorySize, sm11);
    cudaFuncSetAttribute(gemm_tc<1,2,true,false,true,false>,  cudaFuncAttributeMaxDynamicSharedMemorySize, sm12);
    cudaFuncSetAttribute(gemm_tc<2,2,true,true,true,false>,   cudaFuncAttributeMaxDynamicSharedMemorySize, sm22);
    cudaFuncSetAttribute(gemm_tc<2,1,false,true,false,true>,  cudaFuncAttributeMaxDynamicSharedMemorySize, sm21);

    // ---- prep + conv1 (merged, independent work) ----
    prep_conv1_kernel<<<954 + N0_/4, 256>>>(W2, W3, W4, W5, Wu1, Wu2, wh,
                                            points0, neighbors0, features, kpoints, W1, f1);

    gather_mma_kernel<64,8><<<N1_/8, 256>>>(points1, points0, pools0, f1, kpoints, 0.5f, fk, N1_);
    gemm_tc<2,1,true,false,true,false><<<dim3(1,(N1_+127)/128), 256, sm21>>>(fk, wh+WOFF_W2, f2, N1_, 64, 960, nullptr, nullptr, 0, 0, nullptr, nullptr, nullptr);

    gather_mma_kernel<64,8><<<N1_/8, 256>>>(points1, points1, neighbors1, f2, kpoints, 1.0f, fk, N1_);
    gemm_tc<2,2,true,false,true,false><<<dim3(1,(N1_+127)/128), 256, sm22>>>(fk, wh+WOFF_W3, f3, N1_, 128, 960, nullptr, nullptr, 0, 0, nullptr, nullptr, nullptr);

    gather_mma_kernel<128,4><<<(N2_+3)/4, 128>>>(points2, points1, pools1, f3, kpoints, 1.0f, fk, N2_);
    gemm_tc<1,1,true,false,true,false><<<dim3(2,(N2_+63)/64), 256, sm11>>>(fk, wh+WOFF_W4, f4, N2_, 128, 1920, nullptr, nullptr, 0, 0, nullptr, nullptr, nullptr);

    gather_mma_kernel<128,4><<<(N2_+3)/4, 128>>>(points2, points2, neighbors2, f4, kpoints, 2.0f, fk, N2_);
    gemm_tc<1,2,true,false,true,false><<<dim3(2,(N2_+63)/64), 256, sm12>>>(fk, wh+WOFF_W5, f5, N2_, 256, 1920, nullptr, nullptr, 0, 0, nullptr, nullptr, nullptr);

    // ---- decoder (concat fused into GEMM A-load; U2 also emits fnorm + stats) ----
    gemm_tc<2,2,true,true,true,false><<<dim3(1,(N1_+127)/128), 256, sm22>>>(f5, wh+WOFF_U1, fu1, N1_, 128, 384,
                                                                            upsamples1, f3, 256, 128, nullptr, nullptr, nullptr);
    gemm_tc<2,1,false,true,false,true><<<dim3(1,(N0_+127)/128), 256, sm21>>>(fu1, wh+WOFF_U2, ff, N0_, 32, 192,
                                                                             upsamples0, f1, 128, 64, rsnz, gmaxp, out);

    // ---- detection head (score-only; fnorm already written by U2) ----
    scores_kernel<<<(N0_ + 7)/8, 256>>>(neighbors0, ff, rsnz, out + (size_t)N0_*32);
}